// round 15
// baseline (speedup 1.0000x reference)
#include <cuda_runtime.h>
#include <cuda_bf16.h>
#include <cstdint>

#define BATCH   8
#define SEQ     4096
#define NQ      (BATCH * SEQ)       // 32768
#define NTILE   32                  // 128-row tiles per batch
#define NPAIR   528                 // NTILE*(NTILE+1)/2
#define QPB     128
#define KST     136                 // sKt row stride (floats)
#define VST     136                 // sV row stride (bf16)
#define WST     136                 // sW row stride (bf16)
#define PSTR    4                   // uint32 words per O record (16B, uint4-aligned)

// __device__ scratch (no allocs allowed)
__device__ float          g_qT [8 * NQ];   // tf32-rounded cos, [dim][key]
__device__ __nv_bfloat16  g_qTb[8 * NQ];   // bf16 cos,         [dim][key]
__device__ __align__(16) uint32_t g_part[(size_t)NTILE * NQ * PSTR];  // 16.8 MB O partials
__device__ float          g_den [(size_t)NTILE * NQ];                 // 4.2 MB den partials
__device__ int            g_cnt [BATCH * NTILE];                      // arrival counters

#define ONESB 0x3F803F80u   // bf16x2 (1.0, 1.0)

__device__ __forceinline__ uint32_t tf32r(float x) {
    uint32_t r; asm("cvt.rna.tf32.f32 %0, %1;" : "=r"(r) : "f"(x)); return r;
}
__device__ __forceinline__ float ex2f(float x) {
    float r; asm("ex2.approx.f32 %0, %1;" : "=f"(r) : "f"(x)); return r;
}
__device__ __forceinline__ uint32_t bf16x2(float hi, float lo) {
    uint32_t r; asm("cvt.rn.bf16x2.f32 %0, %1, %2;" : "=r"(r) : "f"(hi), "f"(lo)); return r;
}
__device__ __forceinline__ uint32_t f16x2(float hi, float lo) {
    uint32_t r; asm("cvt.rn.f16x2.f32 %0, %1, %2;" : "=r"(r) : "f"(hi), "f"(lo)); return r;
}
__device__ __forceinline__ float2 f16x2_unpack(uint32_t v) {
    __half2 h = *(__half2*)&v;
    return __half22float2(h);
}
__device__ __forceinline__ uint32_t smem_u32(const void* p) {
    uint32_t a;
    asm("{ .reg .u64 t; cvta.to.shared.u64 t, %1; cvt.u32.u64 %0, t; }" : "=r"(a) : "l"(p));
    return a;
}

__device__ __forceinline__ void mma_tf32(float s[4],
        uint32_t a0, uint32_t a1, uint32_t a2, uint32_t a3,
        uint32_t b0, uint32_t b1) {
    asm("mma.sync.aligned.m16n8k8.row.col.f32.tf32.tf32.f32 "
        "{%0,%1,%2,%3},{%4,%5,%6,%7},{%8,%9},{%10,%11,%12,%13};"
        : "=f"(s[0]), "=f"(s[1]), "=f"(s[2]), "=f"(s[3])
        : "r"(a0), "r"(a1), "r"(a2), "r"(a3), "r"(b0), "r"(b1),
          "f"(0.0f), "f"(0.0f), "f"(0.0f), "f"(0.0f));
}
__device__ __forceinline__ void mma_bf16(float o[4],
        uint32_t a0, uint32_t a1, uint32_t a2, uint32_t a3,
        uint32_t b0, uint32_t b1) {
    asm("mma.sync.aligned.m16n8k16.row.col.f32.bf16.bf16.f32 "
        "{%0,%1,%2,%3},{%4,%5,%6,%7},{%8,%9},{%0,%1,%2,%3};"
        : "+f"(o[0]), "+f"(o[1]), "+f"(o[2]), "+f"(o[3])
        : "r"(a0), "r"(a1), "r"(a2), "r"(a3), "r"(b0), "r"(b1));
}
__device__ __forceinline__ void ldmx2(uint32_t& r0, uint32_t& r1, uint32_t addr) {
    asm("ldmatrix.sync.aligned.m8n8.x2.shared.b16 {%0,%1}, [%2];"
        : "=r"(r0), "=r"(r1) : "r"(addr));
}
__device__ __forceinline__ void ldmx4t(uint32_t& r0, uint32_t& r1, uint32_t& r2, uint32_t& r3,
                                       uint32_t addr) {
    asm("ldmatrix.sync.aligned.m8n8.x4.trans.shared.b16 {%0,%1,%2,%3}, [%4];"
        : "=r"(r0), "=r"(r1), "=r"(r2), "=r"(r3) : "r"(addr));
}

// ---------------------------------------------------------------------------
// Kernel 1: cos(x+theta) -> g_qT (tf32) / g_qTb (bf16); zero tile counters.
// ---------------------------------------------------------------------------
__global__ void k_prep(const float* __restrict__ x, const float* __restrict__ theta) {
    int key = blockIdx.x * blockDim.x + threadIdx.x;
    if (key >= NQ) return;
    if (key < BATCH * NTILE) g_cnt[key] = 0;
    float th[8];
#pragma unroll
    for (int d = 0; d < 8; ++d) th[d] = theta[d];
    const float4* xp = (const float4*)(x + (size_t)key * 8);
    float4 a = xp[0], b = xp[1];
    float xv[8] = {a.x, a.y, a.z, a.w, b.x, b.y, b.z, b.w};
#pragma unroll
    for (int d = 0; d < 8; ++d) {
        float v = __cosf(xv[d] + th[d]);
        g_qT [d * NQ + key] = __uint_as_float(tf32r(v));
        g_qTb[d * NQ + key] = __float2bfloat16(v);
    }
}

// ---------------------------------------------------------------------------
// Tail reducer: one CTA reduces one query-tile (128 queries x 32 slots),
// normalizes, applies W_out^T (staged in sKt by caller), writes out.
// Partials are L2-hot (just written by peer CTAs).
// ---------------------------------------------------------------------------
__device__ void reduce_tile(int b, int t, int tid, const float* sw,
                            float* __restrict__ out) {
    const int q = b * SEQ + t * 128 + tid;
    float acc[8] = {0, 0, 0, 0, 0, 0, 0, 0};
    float den = 0.0f;
#pragma unroll 8
    for (int s = 0; s < NTILE; ++s) {
        uint4 w = *(const uint4*)(g_part + ((size_t)s * NQ + q) * PSTR);
        float2 f0 = f16x2_unpack(w.x);
        float2 f1 = f16x2_unpack(w.y);
        float2 f2 = f16x2_unpack(w.z);
        float2 f3 = f16x2_unpack(w.w);
        acc[0] += f0.x; acc[1] += f0.y; acc[2] += f1.x; acc[3] += f1.y;
        acc[4] += f2.x; acc[5] += f2.y; acc[6] += f3.x; acc[7] += f3.y;
        den += g_den[(size_t)s * NQ + q];
    }
    float inv = 1.0f / den;
    float ov[8];
#pragma unroll
    for (int d = 0; d < 8; ++d) ov[d] = acc[d] * inv;
    float r[8];
#pragma unroll
    for (int e = 0; e < 8; ++e) {
        float s = 0.0f;
#pragma unroll
        for (int d = 0; d < 8; ++d) s = fmaf(ov[d], sw[e * 8 + d], s);
        r[e] = s;
    }
    float4* op = (float4*)(out + (size_t)q * 8);
    op[0] = make_float4(r[0], r[1], r[2], r[3]);
    op[1] = make_float4(r[4], r[5], r[6], r[7]);
}

// ---------------------------------------------------------------------------
// Kernel 2: symmetric-pair attention (R14 core) + fused last-arriver finisher.
// ---------------------------------------------------------------------------
__global__ void __launch_bounds__(QPB) k_attn(const float* __restrict__ W,
                                              float* __restrict__ out) {
    __shared__ __align__(16) float         sKt[8 * KST];     // K tile j tf32 [dim][key]
    __shared__ __align__(16) __nv_bfloat16 sVj[8 * VST];     // V tile j bf16 [dim][key]
    __shared__ __align__(16) __nv_bfloat16 sVi[8 * VST];     // V tile i bf16 [dim][key]
    __shared__ __align__(16) __nv_bfloat16 sW [128 * WST];   // P tile bf16 [qi][kj]
    __shared__ int sRed[2];

    const int tid  = threadIdx.x;
    const int lane = tid & 31;
    const int warp = tid >> 5;
    const int g    = lane >> 2;
    const int tid4 = lane & 3;

    // ---- decode (b, i, j) from triangular pair index ----
    const int b = blockIdx.y;
    const int p = blockIdx.x;
    int i = (int)((65.0f - sqrtf(4225.0f - 8.0f * (float)p)) * 0.5f);
    if (i > 31) i = 31;
    while (i > 0 && (i * (65 - i)) / 2 > p) --i;
    while (((i + 1) * (64 - i)) / 2 <= p) ++i;
    const int j = i + (p - (i * (65 - i)) / 2);

    const int ki0 = b * SEQ + i * 128;
    const int kj0 = b * SEQ + j * 128;
    const bool offdiag = (i != j);

    // ---- fill smem tiles ----
    for (int idx = tid; idx < 256; idx += QPB) {      // sKt: 8 dims x 32 float4
        int d = idx >> 5, c = idx & 31;
        ((float4*)(sKt + d * KST))[c] = ((const float4*)(g_qT + d * NQ + kj0))[c];
    }
    for (int idx = tid; idx < 256; idx += QPB) {      // sVj + sVi
        int d = (idx >> 4) & 7, c = idx & 15;
        if (idx < 128)
            ((uint4*)(sVj + d * VST))[c] = ((const uint4*)(g_qTb + d * NQ + kj0))[c];
        else
            ((uint4*)(sVi + d * VST))[c] = ((const uint4*)(g_qTb + d * NQ + ki0))[c];
    }

    // ---- Q fragments (tile i rows), scaled by log2(e)/sqrt(8), tf32 ----
    const float SCALE = 0.51006310094284079f;
    uint32_t qa0[2], qa1[2], qa2[2], qa3[2];
#pragma unroll
    for (int mt = 0; mt < 2; ++mt) {
        int r0 = ki0 + warp * 32 + mt * 16 + g;
        qa0[mt] = tf32r(g_qT[tid4 * NQ + r0] * SCALE);
        qa1[mt] = tf32r(g_qT[tid4 * NQ + r0 + 8] * SCALE);
        qa2[mt] = tf32r(g_qT[(tid4 + 4) * NQ + r0] * SCALE);
        qa3[mt] = tf32r(g_qT[(tid4 + 4) * NQ + r0 + 8] * SCALE);
    }
    __syncthreads();

    const int vrow = lane & 7;
    const int voff = ((lane & 15) >= 8) ? 8 : 0;
    const uint32_t vbj = smem_u32(sVj + vrow * VST + voff);
    const uint32_t vbi = smem_u32(sVi + vrow * VST + voff);
    uint32_t* sW32 = (uint32_t*)sW;

    float o[2][4]   = {{0, 0, 0, 0}, {0, 0, 0, 0}};
    float dn1[2][2] = {{0, 0}, {0, 0}};   // [mt][row g / row g+8]

    // ======== Phase 1: direct direction ========
#pragma unroll 2
    for (int s = 0; s < 8; ++s) {
        const int k0 = s * 16;
        uint32_t b0a = __float_as_uint(sKt[tid4 * KST + k0 + g]);
        uint32_t b1a = __float_as_uint(sKt[(tid4 + 4) * KST + k0 + g]);
        uint32_t b0b = __float_as_uint(sKt[tid4 * KST + k0 + 8 + g]);
        uint32_t b1b = __float_as_uint(sKt[(tid4 + 4) * KST + k0 + 8 + g]);
        uint32_t vb0, vb1;
        ldmx2(vb0, vb1, vbj + (uint32_t)k0 * 2);

#pragma unroll
        for (int mt = 0; mt < 2; ++mt) {
            float s1[4], s2[4];
            mma_tf32(s1, qa0[mt], qa1[mt], qa2[mt], qa3[mt], b0a, b1a);
            mma_tf32(s2, qa0[mt], qa1[mt], qa2[mt], qa3[mt], b0b, b1b);
#pragma unroll
            for (int t = 0; t < 4; ++t) { s1[t] = ex2f(s1[t]); s2[t] = ex2f(s2[t]); }
            dn1[mt][0] += (s1[0] + s1[1]) + (s2[0] + s2[1]);
            dn1[mt][1] += (s1[2] + s1[3]) + (s2[2] + s2[3]);
            uint32_t pa0 = bf16x2(s1[1], s1[0]);
            uint32_t pa1 = bf16x2(s1[3], s1[2]);
            uint32_t pa2 = bf16x2(s2[1], s2[0]);
            uint32_t pa3 = bf16x2(s2[3], s2[2]);
            if (offdiag) {   // store P tile for phase 2
                int row0 = warp * 32 + mt * 16 + g;
                sW32[row0 * (WST / 2) + (k0 >> 1) + tid4]             = pa0;
                sW32[(row0 + 8) * (WST / 2) + (k0 >> 1) + tid4]       = pa1;
                sW32[row0 * (WST / 2) + ((k0 + 8) >> 1) + tid4]       = pa2;
                sW32[(row0 + 8) * (WST / 2) + ((k0 + 8) >> 1) + tid4] = pa3;
            }
            mma_bf16(o[mt], pa0, pa1, pa2, pa3, vb0, vb1);
        }
    }

    // quad-reduce den over the 4 col-threads
#pragma unroll
    for (int mt = 0; mt < 2; ++mt) {
#pragma unroll
        for (int r = 0; r < 2; ++r) {
            dn1[mt][r] += __shfl_xor_sync(0xFFFFFFFF, dn1[mt][r], 1);
            dn1[mt][r] += __shfl_xor_sync(0xFFFFFFFF, dn1[mt][r], 2);
        }
    }

    // ---- phase-1 partial writes (fp16 O; den to g_den): queries tile i, slot j ----
#pragma unroll
    for (int mt = 0; mt < 2; ++mt) {
        int q0 = ki0 + warp * 32 + mt * 16 + g;
        uint32_t* pp = g_part + ((size_t)j * NQ + q0) * PSTR;
        pp[tid4] = f16x2(o[mt][1], o[mt][0]);
        if (tid4 == 0) g_den[(size_t)j * NQ + q0] = dn1[mt][0];
        uint32_t* pq = g_part + ((size_t)j * NQ + q0 + 8) * PSTR;
        pq[tid4] = f16x2(o[mt][3], o[mt][2]);
        if (tid4 == 0) g_den[(size_t)j * NQ + q0 + 8] = dn1[mt][1];
    }

    // ======== Phase 2: transposed direction (off-diagonal only) ========
    if (offdiag) {
        __syncthreads();   // sW complete
        float o2[2][4]  = {{0, 0, 0, 0}, {0, 0, 0, 0}};
        float dn2[2][4] = {{0, 0, 0, 0}, {0, 0, 0, 0}};

        const int lr   = lane & 7;
        const int sel  = lane >> 3;
        const int rowb = lr + ((sel & 2) ? 8 : 0);
        const int colb = warp * 32 + ((sel & 1) ? 8 : 0);
        const uint32_t sWu = smem_u32(sW);

#pragma unroll 2
        for (int s = 0; s < 8; ++s) {
            const int c0 = s * 16;
            uint32_t vb0, vb1;
            ldmx2(vb0, vb1, vbi + (uint32_t)c0 * 2);
#pragma unroll
            for (int mt = 0; mt < 2; ++mt) {
                uint32_t a0, a1, a2, a3;
                ldmx4t(a0, a1, a2, a3,
                       sWu + (uint32_t)(((c0 + rowb) * WST + colb + mt * 16) * 2));
                mma_bf16(o2[mt],  a0, a1, a2, a3, vb0, vb1);
                mma_bf16(dn2[mt], a0, a1, a2, a3, ONESB, ONESB);
            }
        }

        // writes: queries tile j, slot i
#pragma unroll
        for (int mt = 0; mt < 2; ++mt) {
            int q0 = kj0 + warp * 32 + mt * 16 + g;
            uint32_t* pp = g_part + ((size_t)i * NQ + q0) * PSTR;
            pp[tid4] = f16x2(o2[mt][1], o2[mt][0]);
            if (tid4 == 0) g_den[(size_t)i * NQ + q0] = dn2[mt][0];
            uint32_t* pq = g_part + ((size_t)i * NQ + q0 + 8) * PSTR;
            pq[tid4] = f16x2(o2[mt][3], o2[mt][2]);
            if (tid4 == 0) g_den[(size_t)i * NQ + q0 + 8] = dn2[mt][2];
        }
    }

    // ======== Fused finisher: last arriver per tile reduces it ========
    __threadfence();          // partial writes visible before counter bump
    __syncthreads();          // all warps' writes issued
    if (tid == 0) {
        sRed[0] = (atomicAdd(&g_cnt[b * NTILE + i], 1) == NTILE - 1);
        sRed[1] = offdiag ? (atomicAdd(&g_cnt[b * NTILE + j], 1) == NTILE - 1) : 0;
    }
    __syncthreads();

    if (sRed[0] | sRed[1]) {
        // stage W_out into (now dead) sKt
        if (tid < 64) sKt[tid] = W[tid];
        __syncthreads();
        if (sRed[0]) reduce_tile(b, i, tid, sKt, out);
        if (sRed[1]) reduce_tile(b, j, tid, sKt, out);
    }
}

// ---------------------------------------------------------------------------
extern "C" void kernel_launch(void* const* d_in, const int* in_sizes, int n_in,
                              void* d_out, int out_size) {
    const float* x     = (const float*)d_in[0];   // [8,4096,8] f32
    const float* theta = (const float*)d_in[1];   // [8] f32
    const float* W_out = (const float*)d_in[2];   // [8,8] f32
    float* out = (float*)d_out;                   // [8,4096,8] f32

    k_prep<<<(NQ + 255) / 256, 256>>>(x, theta);
    k_attn<<<dim3(NPAIR, BATCH), QPB>>>(W_out, out);
}

// round 16
// speedup vs baseline: 1.1658x; 1.1658x over previous
#include <cuda_runtime.h>
#include <cuda_bf16.h>
#include <cstdint>

#define BATCH   8
#define SEQ     4096
#define NQ      (BATCH * SEQ)       // 32768
#define NTILE   32                  // 128-row tiles per batch
#define NPAIR   528                 // NTILE*(NTILE+1)/2
#define QPB     128
#define KST     136                 // sKt row stride (floats)
#define VST     136                 // sV row stride (bf16)
#define WST     136                 // sW row stride (bf16)
#define PSTR    4                   // uint32 words per O record (16B, uint4-aligned)

// __device__ scratch (no allocs allowed)
__device__ float          g_qT [8 * NQ];   // tf32-rounded cos, [dim][key]
__device__ __nv_bfloat16  g_qTb[8 * NQ];   // bf16 cos,         [dim][key]
__device__ __align__(16) uint32_t g_part[(size_t)NTILE * NQ * PSTR];  // 16.8 MB O partials
__device__ float          g_den [(size_t)NTILE * NQ];                 // 4.2 MB den partials

#define ONESB 0x3F803F80u   // bf16x2 (1.0, 1.0)

__device__ __forceinline__ uint32_t tf32r(float x) {
    uint32_t r; asm("cvt.rna.tf32.f32 %0, %1;" : "=r"(r) : "f"(x)); return r;
}
__device__ __forceinline__ float ex2f(float x) {
    float r; asm("ex2.approx.f32 %0, %1;" : "=f"(r) : "f"(x)); return r;
}
__device__ __forceinline__ uint32_t bf16x2(float hi, float lo) {
    uint32_t r; asm("cvt.rn.bf16x2.f32 %0, %1, %2;" : "=r"(r) : "f"(hi), "f"(lo)); return r;
}
__device__ __forceinline__ uint32_t f16x2(float hi, float lo) {
    uint32_t r; asm("cvt.rn.f16x2.f32 %0, %1, %2;" : "=r"(r) : "f"(hi), "f"(lo)); return r;
}
__device__ __forceinline__ float2 f16x2_unpack(uint32_t v) {
    __half2 h = *(__half2*)&v;
    return __half22float2(h);
}
__device__ __forceinline__ uint32_t smem_u32(const void* p) {
    uint32_t a;
    asm("{ .reg .u64 t; cvta.to.shared.u64 t, %1; cvt.u32.u64 %0, t; }" : "=r"(a) : "l"(p));
    return a;
}

__device__ __forceinline__ void mma_tf32(float s[4],
        uint32_t a0, uint32_t a1, uint32_t a2, uint32_t a3,
        uint32_t b0, uint32_t b1) {
    asm("mma.sync.aligned.m16n8k8.row.col.f32.tf32.tf32.f32 "
        "{%0,%1,%2,%3},{%4,%5,%6,%7},{%8,%9},{%10,%11,%12,%13};"
        : "=f"(s[0]), "=f"(s[1]), "=f"(s[2]), "=f"(s[3])
        : "r"(a0), "r"(a1), "r"(a2), "r"(a3), "r"(b0), "r"(b1),
          "f"(0.0f), "f"(0.0f), "f"(0.0f), "f"(0.0f));
}
__device__ __forceinline__ void mma_bf16(float o[4],
        uint32_t a0, uint32_t a1, uint32_t a2, uint32_t a3,
        uint32_t b0, uint32_t b1) {
    asm("mma.sync.aligned.m16n8k16.row.col.f32.bf16.bf16.f32 "
        "{%0,%1,%2,%3},{%4,%5,%6,%7},{%8,%9},{%0,%1,%2,%3};"
        : "+f"(o[0]), "+f"(o[1]), "+f"(o[2]), "+f"(o[3])
        : "r"(a0), "r"(a1), "r"(a2), "r"(a3), "r"(b0), "r"(b1));
}
__device__ __forceinline__ void ldmx2(uint32_t& r0, uint32_t& r1, uint32_t addr) {
    asm("ldmatrix.sync.aligned.m8n8.x2.shared.b16 {%0,%1}, [%2];"
        : "=r"(r0), "=r"(r1) : "r"(addr));
}
__device__ __forceinline__ void ldmx4t(uint32_t& r0, uint32_t& r1, uint32_t& r2, uint32_t& r3,
                                       uint32_t addr) {
    asm("ldmatrix.sync.aligned.m8n8.x4.trans.shared.b16 {%0,%1,%2,%3}, [%4];"
        : "=r"(r0), "=r"(r1), "=r"(r2), "=r"(r3) : "r"(addr));
}

// ---------------------------------------------------------------------------
// Kernel 1: cos(x+theta) -> g_qT (tf32, [dim][key]) and g_qTb (bf16). 1 key/thread.
// ---------------------------------------------------------------------------
__global__ void k_prep(const float* __restrict__ x, const float* __restrict__ theta) {
    int key = blockIdx.x * blockDim.x + threadIdx.x;
    if (key >= NQ) return;
    float th[8];
#pragma unroll
    for (int d = 0; d < 8; ++d) th[d] = theta[d];
    const float4* xp = (const float4*)(x + (size_t)key * 8);
    float4 a = xp[0], b = xp[1];
    float xv[8] = {a.x, a.y, a.z, a.w, b.x, b.y, b.z, b.w};
#pragma unroll
    for (int d = 0; d < 8; ++d) {
        float v = __cosf(xv[d] + th[d]);
        g_qT [d * NQ + key] = __uint_as_float(tf32r(v));
        g_qTb[d * NQ + key] = __float2bfloat16(v);
    }
}

// ---------------------------------------------------------------------------
// Kernel 2: symmetric-pair attention (R14 core). Occupancy raised via
// __launch_bounds__(128, 6): ncu showed issue=56% / occ=29% / no pipe >28%,
// i.e. scheduler starved for eligible warps, not for any unit.
// ---------------------------------------------------------------------------
__global__ void __launch_bounds__(QPB, 6) k_attn() {
    __shared__ __align__(16) float         sKt[8 * KST];     // K tile j tf32 [dim][key]
    __shared__ __align__(16) __nv_bfloat16 sVj[8 * VST];     // V tile j bf16 [dim][key]
    __shared__ __align__(16) __nv_bfloat16 sVi[8 * VST];     // V tile i bf16 [dim][key]
    __shared__ __align__(16) __nv_bfloat16 sW [128 * WST];   // P tile bf16 [qi][kj]

    const int tid  = threadIdx.x;
    const int lane = tid & 31;
    const int warp = tid >> 5;
    const int g    = lane >> 2;
    const int tid4 = lane & 3;

    // ---- decode (b, i, j) from triangular pair index ----
    const int b = blockIdx.y;
    const int p = blockIdx.x;
    int i = (int)((65.0f - sqrtf(4225.0f - 8.0f * (float)p)) * 0.5f);
    if (i > 31) i = 31;
    while (i > 0 && (i * (65 - i)) / 2 > p) --i;
    while (((i + 1) * (64 - i)) / 2 <= p) ++i;
    const int j = i + (p - (i * (65 - i)) / 2);

    const int ki0 = b * SEQ + i * 128;
    const int kj0 = b * SEQ + j * 128;
    const bool offdiag = (i != j);

    // ---- fill smem tiles ----
    for (int idx = tid; idx < 256; idx += QPB) {      // sKt: 8 dims x 32 float4
        int d = idx >> 5, c = idx & 31;
        ((float4*)(sKt + d * KST))[c] = ((const float4*)(g_qT + d * NQ + kj0))[c];
    }
    for (int idx = tid; idx < 256; idx += QPB) {      // sVj + sVi
        int d = (idx >> 4) & 7, c = idx & 15;
        if (idx < 128)
            ((uint4*)(sVj + d * VST))[c] = ((const uint4*)(g_qTb + d * NQ + kj0))[c];
        else
            ((uint4*)(sVi + d * VST))[c] = ((const uint4*)(g_qTb + d * NQ + ki0))[c];
    }

    // ---- Q fragments (tile i rows), scaled by log2(e)/sqrt(8), tf32 ----
    const float SCALE = 0.51006310094284079f;
    uint32_t qa0[2], qa1[2], qa2[2], qa3[2];
#pragma unroll
    for (int mt = 0; mt < 2; ++mt) {
        int r0 = ki0 + warp * 32 + mt * 16 + g;
        qa0[mt] = tf32r(g_qT[tid4 * NQ + r0] * SCALE);
        qa1[mt] = tf32r(g_qT[tid4 * NQ + r0 + 8] * SCALE);
        qa2[mt] = tf32r(g_qT[(tid4 + 4) * NQ + r0] * SCALE);
        qa3[mt] = tf32r(g_qT[(tid4 + 4) * NQ + r0 + 8] * SCALE);
    }
    __syncthreads();

    const int vrow = lane & 7;
    const int voff = ((lane & 15) >= 8) ? 8 : 0;
    const uint32_t vbj = smem_u32(sVj + vrow * VST + voff);
    const uint32_t vbi = smem_u32(sVi + vrow * VST + voff);
    uint32_t* sW32 = (uint32_t*)sW;

    float o[2][4]   = {{0, 0, 0, 0}, {0, 0, 0, 0}};
    float dn1[2][2] = {{0, 0}, {0, 0}};   // [mt][row g / row g+8]

    // ======== Phase 1: direct direction ========
#pragma unroll 2
    for (int s = 0; s < 8; ++s) {
        const int k0 = s * 16;
        uint32_t b0a = __float_as_uint(sKt[tid4 * KST + k0 + g]);
        uint32_t b1a = __float_as_uint(sKt[(tid4 + 4) * KST + k0 + g]);
        uint32_t b0b = __float_as_uint(sKt[tid4 * KST + k0 + 8 + g]);
        uint32_t b1b = __float_as_uint(sKt[(tid4 + 4) * KST + k0 + 8 + g]);
        uint32_t vb0, vb1;
        ldmx2(vb0, vb1, vbj + (uint32_t)k0 * 2);

#pragma unroll
        for (int mt = 0; mt < 2; ++mt) {
            float s1[4], s2[4];
            mma_tf32(s1, qa0[mt], qa1[mt], qa2[mt], qa3[mt], b0a, b1a);
            mma_tf32(s2, qa0[mt], qa1[mt], qa2[mt], qa3[mt], b0b, b1b);
#pragma unroll
            for (int t = 0; t < 4; ++t) { s1[t] = ex2f(s1[t]); s2[t] = ex2f(s2[t]); }
            dn1[mt][0] += (s1[0] + s1[1]) + (s2[0] + s2[1]);
            dn1[mt][1] += (s1[2] + s1[3]) + (s2[2] + s2[3]);
            uint32_t pa0 = bf16x2(s1[1], s1[0]);
            uint32_t pa1 = bf16x2(s1[3], s1[2]);
            uint32_t pa2 = bf16x2(s2[1], s2[0]);
            uint32_t pa3 = bf16x2(s2[3], s2[2]);
            if (offdiag) {   // store P tile for phase 2
                int row0 = warp * 32 + mt * 16 + g;
                sW32[row0 * (WST / 2) + (k0 >> 1) + tid4]             = pa0;
                sW32[(row0 + 8) * (WST / 2) + (k0 >> 1) + tid4]       = pa1;
                sW32[row0 * (WST / 2) + ((k0 + 8) >> 1) + tid4]       = pa2;
                sW32[(row0 + 8) * (WST / 2) + ((k0 + 8) >> 1) + tid4] = pa3;
            }
            mma_bf16(o[mt], pa0, pa1, pa2, pa3, vb0, vb1);
        }
    }

    // quad-reduce den over the 4 col-threads
#pragma unroll
    for (int mt = 0; mt < 2; ++mt) {
#pragma unroll
        for (int r = 0; r < 2; ++r) {
            dn1[mt][r] += __shfl_xor_sync(0xFFFFFFFF, dn1[mt][r], 1);
            dn1[mt][r] += __shfl_xor_sync(0xFFFFFFFF, dn1[mt][r], 2);
        }
    }

    // ---- phase-1 partial writes (fp16 O; den to g_den): queries tile i, slot j ----
#pragma unroll
    for (int mt = 0; mt < 2; ++mt) {
        int q0 = ki0 + warp * 32 + mt * 16 + g;
        uint32_t* pp = g_part + ((size_t)j * NQ + q0) * PSTR;
        pp[tid4] = f16x2(o[mt][1], o[mt][0]);
        if (tid4 == 0) g_den[(size_t)j * NQ + q0] = dn1[mt][0];
        uint32_t* pq = g_part + ((size_t)j * NQ + q0 + 8) * PSTR;
        pq[tid4] = f16x2(o[mt][3], o[mt][2]);
        if (tid4 == 0) g_den[(size_t)j * NQ + q0 + 8] = dn1[mt][1];
    }

    // ======== Phase 2: transposed direction (off-diagonal only) ========
    if (offdiag) {
        __syncthreads();   // sW complete
        float o2[2][4]  = {{0, 0, 0, 0}, {0, 0, 0, 0}};
        float dn2[2][4] = {{0, 0, 0, 0}, {0, 0, 0, 0}};

        const int lr   = lane & 7;
        const int sel  = lane >> 3;
        const int rowb = lr + ((sel & 2) ? 8 : 0);
        const int colb = warp * 32 + ((sel & 1) ? 8 : 0);
        const uint32_t sWu = smem_u32(sW);

#pragma unroll 2
        for (int s = 0; s < 8; ++s) {
            const int c0 = s * 16;
            uint32_t vb0, vb1;
            ldmx2(vb0, vb1, vbi + (uint32_t)c0 * 2);
#pragma unroll
            for (int mt = 0; mt < 2; ++mt) {
                uint32_t a0, a1, a2, a3;
                ldmx4t(a0, a1, a2, a3,
                       sWu + (uint32_t)(((c0 + rowb) * WST + colb + mt * 16) * 2));
                mma_bf16(o2[mt],  a0, a1, a2, a3, vb0, vb1);
                mma_bf16(dn2[mt], a0, a1, a2, a3, ONESB, ONESB);
            }
        }

        // writes: queries tile j, slot i
#pragma unroll
        for (int mt = 0; mt < 2; ++mt) {
            int q0 = kj0 + warp * 32 + mt * 16 + g;
            uint32_t* pp = g_part + ((size_t)i * NQ + q0) * PSTR;
            pp[tid4] = f16x2(o2[mt][1], o2[mt][0]);
            if (tid4 == 0) g_den[(size_t)i * NQ + q0] = dn2[mt][0];
            uint32_t* pq = g_part + ((size_t)i * NQ + q0 + 8) * PSTR;
            pq[tid4] = f16x2(o2[mt][3], o2[mt][2]);
            if (tid4 == 0) g_den[(size_t)i * NQ + q0 + 8] = dn2[mt][2];
        }
    }
}

// ---------------------------------------------------------------------------
// Kernel 3: combine 32 partials/query, normalize, apply W_out^T.
// 4 threads/query, 8 slots each; slot = 1 LDG.128 + 1 LDG.32.
// ---------------------------------------------------------------------------
__global__ void k_fin(const float* __restrict__ W, float* __restrict__ out) {
    __shared__ float sw[64];
    if (threadIdx.x < 64) sw[threadIdx.x] = W[threadIdx.x];
    __syncthreads();

    int idx = blockIdx.x * blockDim.x + threadIdx.x;   // NQ*4 threads
    int q = idx >> 2, sub = idx & 3;
    if (q >= NQ) return;

    float acc[8] = {0, 0, 0, 0, 0, 0, 0, 0};
    float den = 0.0f;
#pragma unroll
    for (int s = 0; s < 8; ++s) {
        const int slot = sub * 8 + s;
        uint4 w = *(const uint4*)(g_part + ((size_t)slot * NQ + q) * PSTR);
        float2 f0 = f16x2_unpack(w.x);
        float2 f1 = f16x2_unpack(w.y);
        float2 f2 = f16x2_unpack(w.z);
        float2 f3 = f16x2_unpack(w.w);
        acc[0] += f0.x; acc[1] += f0.y; acc[2] += f1.x; acc[3] += f1.y;
        acc[4] += f2.x; acc[5] += f2.y; acc[6] += f3.x; acc[7] += f3.y;
        den += g_den[(size_t)slot * NQ + q];
    }
#pragma unroll
    for (int m = 1; m <= 2; m <<= 1) {
#pragma unroll
        for (int d = 0; d < 8; ++d) acc[d] += __shfl_xor_sync(0xFFFFFFFF, acc[d], m);
        den += __shfl_xor_sync(0xFFFFFFFF, den, m);
    }
    if (sub != 0) return;

    float inv = 1.0f / den;
    float ov[8];
#pragma unroll
    for (int d = 0; d < 8; ++d) ov[d] = acc[d] * inv;
    float r[8];
#pragma unroll
    for (int e = 0; e < 8; ++e) {
        float s = 0.0f;
#pragma unroll
        for (int d = 0; d < 8; ++d) s = fmaf(ov[d], sw[e * 8 + d], s);
        r[e] = s;
    }
    float4* op = (float4*)(out + (size_t)q * 8);
    op[0] = make_float4(r[0], r[1], r[2], r[3]);
    op[1] = make_float4(r[4], r[5], r[6], r[7]);
}

// ---------------------------------------------------------------------------
extern "C" void kernel_launch(void* const* d_in, const int* in_sizes, int n_in,
                              void* d_out, int out_size) {
    const float* x     = (const float*)d_in[0];   // [8,4096,8] f32
    const float* theta = (const float*)d_in[1];   // [8] f32
    const float* W_out = (const float*)d_in[2];   // [8,8] f32
    float* out = (float*)d_out;                   // [8,4096,8] f32

    k_prep<<<(NQ + 255) / 256, 256>>>(x, theta);
    k_attn<<<dim3(NPAIR, BATCH), QPB>>>();
    k_fin<<<(NQ * 4 + 255) / 256, 256>>>(W_out, out);
}